// round 16
// baseline (speedup 1.0000x reference)
#include <cuda_runtime.h>
#include <math.h>
#include <stdint.h>

// ---------------------------------------------------------------------------
// GridFeatureToPointGraphConv — R16: fused identical to R15 (best, 148.6us);
// pre_kernel fixed: smem lins table (kills 24 scattered LDGs/thread added by
// the R15 rel-fold). Numerics identical to R15.
// ---------------------------------------------------------------------------

#define RES 48
#define NGRID (RES*RES*RES)      // 110592
#define NPTS 65536
#define KNN 16
#define GPRE_BLKS (NGRID / 64)   // 1728
#define PPRE_BLKS (NPTS / 64)    // 1024

typedef unsigned long long u64;

__device__ float g_Gpre[NGRID * 64];    // 28.3 MB (L2-resident)
__device__ u64   g_Ppre[NPTS * 32];     // 16 MB
__device__ uint2 g_W2frag[8 * 32 * 4];  // per-lane tf32 B fragments [s][lane][nt]
__device__ u64   g_W3p[16 * 32];        // {W3[2i][o], W3[2i+1][o]}

// ---- f32x2 helpers -------------------------------------------------------
__device__ __forceinline__ u64 pack2(float lo, float hi) {
    u64 r; asm("mov.b64 %0, {%1,%2};" : "=l"(r) : "f"(lo), "f"(hi)); return r;
}
__device__ __forceinline__ void unpack2(u64 v, float& lo, float& hi) {
    asm("mov.b64 {%0,%1}, %2;" : "=f"(lo), "=f"(hi) : "l"(v));
}
__device__ __forceinline__ u64 fma2(u64 a, u64 b, u64 c) {
    u64 d; asm("fma.rn.f32x2 %0, %1, %2, %3;" : "=l"(d) : "l"(a), "l"(b), "l"(c)); return d;
}
__device__ __forceinline__ u64 mul2(u64 a, u64 b) {
    u64 d; asm("mul.rn.f32x2 %0, %1, %2;" : "=l"(d) : "l"(a), "l"(b)); return d;
}
__device__ __forceinline__ u64 add2(u64 a, u64 b) {
    u64 d; asm("add.rn.f32x2 %0, %1, %2;" : "=l"(d) : "l"(a), "l"(b)); return d;
}
__device__ __forceinline__ float ex2f(float x) {
    float r; asm("ex2.approx.f32 %0, %1;" : "=f"(r) : "f"(x)); return r;
}
__device__ __forceinline__ float rcpf(float x) {
    float r; asm("rcp.approx.f32 %0, %1;" : "=f"(r) : "f"(x)); return r;
}
__device__ __forceinline__ uint32_t s2u(const void* p) {
    return (uint32_t)__cvta_generic_to_shared(p);
}
__device__ __forceinline__ uint32_t tf32r(float x) {
    uint32_t r; asm("cvt.rna.tf32.f32 %0, %1;" : "=r"(r) : "f"(x)); return r;
}

// gelu_tanh(x) == x / (1 + e^{-p}), p = 1.5957691216x + 0.07135481681x^3
__device__ __forceinline__ float gelu_fast(float x) {
    float u = x * x;
    float w = __fmaf_rn(0.07135481681f, u, 1.5957691216f);
    float p = x * w;
    float e = __expf(-p);
    return __fdividef(x, 1.0f + e);
}
// paired gelu with -log2e folded into the polynomial
__device__ __forceinline__ u64 gelu2(u64 x) {
    const u64 C0 = pack2(-0.10295047642f, -0.10295047642f);
    const u64 C1 = pack2(-2.30258509299f, -2.30258509299f);
    const u64 ONE2 = pack2(1.0f, 1.0f);
    u64 u = mul2(x, x);
    u64 w = fma2(u, C0, C1);
    u64 m = mul2(x, w);
    float m0, m1; unpack2(m, m0, m1);
    u64 e = pack2(ex2f(m0), ex2f(m1));
    u64 den = add2(ONE2, e);
    float d0, d1; unpack2(den, d0, d1);
    u64 r = pack2(rcpf(d0), rcpf(d1));
    return mul2(x, r);
}

// tf32 mma m16n8k8
__device__ __forceinline__ void mma_tf32(float& d0, float& d1, float& d2, float& d3,
                                         uint32_t a0, uint32_t a1, uint32_t a2, uint32_t a3,
                                         uint32_t b0, uint32_t b1) {
    asm volatile(
        "mma.sync.aligned.m16n8k8.row.col.f32.tf32.tf32.f32 "
        "{%0,%1,%2,%3}, {%4,%5,%6,%7}, {%8,%9}, {%0,%1,%2,%3};"
        : "+f"(d0), "+f"(d1), "+f"(d2), "+f"(d3)
        : "r"(a0), "r"(a1), "r"(a2), "r"(a3), "r"(b0), "r"(b1));
}

// ---------------------------------------------------------------------------
// Kernel 1: merged pre-processing with rel-position folding (smem lins).
// ---------------------------------------------------------------------------
__global__ __launch_bounds__(256) void pre_kernel(const float* __restrict__ gf,
                                                  const float* __restrict__ pf,
                                                  const float* __restrict__ gv,
                                                  const float* __restrict__ pv,
                                                  const float* __restrict__ W1,
                                                  const float* __restrict__ b1,
                                                  const float* __restrict__ W2,
                                                  const float* __restrict__ W3) {
    __shared__ float linsS[RES];
    const int tid = threadIdx.x;
    const int bid = blockIdx.x;
    const int v = tid >> 5;
    const int o = tid & 31;

    if (tid < RES) linsS[tid] = __fmul_rn(__ldg(&gv[3 * tid + 2]), 24.0f);

    if (bid == 0) {
        for (int j = tid; j < 8 * 32 * 4; j += 256) {
            int s = j >> 7, ln = (j >> 2) & 31, nt = j & 3;
            int t = ln & 3, g = ln >> 2;
            uint2 vv;
            vv.x = tf32r(W2[(8 * s + t) * 32 + 8 * nt + g]);
            vv.y = tf32r(W2[(8 * s + t + 4) * 32 + 8 * nt + g]);
            g_W2frag[j] = vv;
        }
        for (int j = tid; j < 16 * 32; j += 256) {
            int i = j >> 5, oo = j & 31;
            g_W3p[j] = pack2(W3[(2 * i) * 32 + oo], W3[(2 * i + 1) * 32 + oo]);
        }
    }

    // rel-row pairs for this lane's channel pair
    const u64 wrx = pack2(W1[64 * 64 + 2 * o], W1[64 * 64 + 2 * o + 1]);
    const u64 wry = pack2(W1[65 * 64 + 2 * o], W1[65 * 64 + 2 * o + 1]);
    const u64 wrz = pack2(W1[66 * 64 + 2 * o], W1[66 * 64 + 2 * o + 1]);

    __syncthreads();

    if (bid < GPRE_BLKS) {
        u64 wcol[32];
        #pragma unroll
        for (int c = 0; c < 32; ++c)
            wcol[c] = __ldg(reinterpret_cast<const u64*>(W1 + c * 64 + 2 * o));
        const int base = bid * 64;
        u64* Gpreu = reinterpret_cast<u64*>(g_Gpre);
        #pragma unroll
        for (int pass = 0; pass < 8; ++pass) {
            const int g = base + pass * 8 + v;
            const float4* grow = reinterpret_cast<const float4*>(gf + (size_t)g * 32);
            u64 acc = pack2(0.0f, 0.0f);
            #pragma unroll
            for (int c4 = 0; c4 < 8; ++c4) {
                float4 f = __ldg(&grow[c4]);
                acc = fma2(pack2(f.x, f.x), wcol[4 * c4 + 0], acc);
                acc = fma2(pack2(f.y, f.y), wcol[4 * c4 + 1], acc);
                acc = fma2(pack2(f.z, f.z), wcol[4 * c4 + 2], acc);
                acc = fma2(pack2(f.w, f.w), wcol[4 * c4 + 3], acc);
            }
            // fold + lins[ix]*W1rx + lins[iy]*W1ry + lins[iz]*W1rz (smem LDS)
            int ixg = g / (RES * RES);
            int rem = g - ixg * (RES * RES);
            int iyg = rem / RES;
            int izg = rem - iyg * RES;
            float lx = linsS[ixg];
            float ly = linsS[iyg];
            float lz = linsS[izg];
            acc = fma2(pack2(lx, lx), wrx, acc);
            acc = fma2(pack2(ly, ly), wry, acc);
            acc = fma2(pack2(lz, lz), wrz, acc);
            Gpreu[(size_t)g * 32 + o] = acc;
        }
    } else {
        u64 wcol[32];
        #pragma unroll
        for (int c = 0; c < 32; ++c)
            wcol[c] = __ldg(reinterpret_cast<const u64*>(W1 + (32 + c) * 64 + 2 * o));
        const u64 b1v = __ldg(reinterpret_cast<const u64*>(b1 + 2 * o));
        const int base = (bid - GPRE_BLKS) * 64;
        #pragma unroll
        for (int pass = 0; pass < 8; ++pass) {
            const int p = base + pass * 8 + v;
            const float4* prow = reinterpret_cast<const float4*>(pf + (size_t)p * 32);
            u64 acc = b1v;
            #pragma unroll
            for (int c4 = 0; c4 < 8; ++c4) {
                float4 f = __ldg(&prow[c4]);
                acc = fma2(pack2(f.x, f.x), wcol[4 * c4 + 0], acc);
                acc = fma2(pack2(f.y, f.y), wcol[4 * c4 + 1], acc);
                acc = fma2(pack2(f.z, f.z), wcol[4 * c4 + 2], acc);
                acc = fma2(pack2(f.w, f.w), wcol[4 * c4 + 3], acc);
            }
            // fold - qx*W1rx - qy*W1ry - qz*W1rz
            float nqx = __fmul_rn(__ldg(&pv[3 * p + 0]), -24.0f);
            float nqy = __fmul_rn(__ldg(&pv[3 * p + 1]), -24.0f);
            float nqz = __fmul_rn(__ldg(&pv[3 * p + 2]), -24.0f);
            acc = fma2(pack2(nqx, nqx), wrx, acc);
            acc = fma2(pack2(nqy, nqy), wry, acc);
            acc = fma2(pack2(nqz, nqz), wrz, acc);
            g_Ppre[(size_t)p * 32 + o] = acc;
        }
    }
}

// ---------------------------------------------------------------------------
// Selection helpers — 32-bit keys, set-only top-16 (R14)
// ---------------------------------------------------------------------------
__device__ __forceinline__ float cand_dist(int t, int ix0, int iy0, int iz0,
                                           const float* __restrict__ lins,
                                           float qx, float qy, float qz, float qq) {
    int a = t >> 4, b = (t >> 2) & 3, c = t & 3;
    float px = lins[ix0 + a], py = lins[iy0 + b], pz = lins[iz0 + c];
    float pp = __fadd_rn(__fadd_rn(__fmul_rn(px, px), __fmul_rn(py, py)), __fmul_rn(pz, pz));
    float dot = __fmaf_rn(qz, pz, __fmaf_rn(qy, py, __fmul_rn(qx, px)));
    return __fadd_rn(__fsub_rn(qq, __fadd_rn(dot, dot)), pp);
}
__device__ __forceinline__ unsigned int fmap(float d) {
    unsigned int b = __float_as_uint(d);
    return (b & 0x80000000u) ? ~b : (b | 0x80000000u);
}
__device__ __forceinline__ unsigned int ce32(unsigned int k, int j, bool up, int lane) {
    unsigned int pk = __shfl_xor_sync(0xffffffffu, k, j);
    unsigned int mn = min(k, pk);
    unsigned int mx = max(k, pk);
    bool lower = ((lane & j) == 0);
    return (lower == up) ? mn : mx;
}

// ---------------------------------------------------------------------------
// Kernel 2: fused. One warp per point; layer-2 via mma.sync tf32.
// ---------------------------------------------------------------------------
__global__ __launch_bounds__(256, 4) void fused_kernel(
    const float* __restrict__ gv,
    const float* __restrict__ pv,
    const float* __restrict__ b2,
    const float* __restrict__ b3,
    float* __restrict__ out)
{
    __shared__ float lins[RES];
    __shared__ float b2s[32];
    __shared__ float b3s[32];
    __shared__ __align__(16) uint2 frs[8 * 32 * 4];       // W2 fragments (8 KB)
    __shared__ __align__(16) uint32_t h1s[8][16 * 64];    // tf32 h1, XOR-swizzled
    __shared__ __align__(16) u64 aggs[8][16];
    __shared__ int gms[8][16];

    int tid = threadIdx.x;
    for (int j = tid; j < 8 * 32 * 4; j += 256) frs[j] = __ldg(&g_W2frag[j]);
    if (tid >= 128 && tid < 160) b2s[tid - 128] = b2[tid - 128];
    if (tid >= 160 && tid < 192) b3s[tid - 160] = b3[tid - 160];
    if (tid >= 192 && tid < 192 + RES)
        lins[tid - 192] = __fmul_rn(gv[3 * (tid - 192) + 2], 24.0f);
    __syncthreads();

    const int w = tid >> 5;
    const int lane = tid & 31;
    const int p = blockIdx.x * 8 + w;
    const int t4 = lane & 3;
    const int g4 = lane >> 2;

    // per-point layer-1 partial (precomputed, rel q-part folded in)
    u64 pre2 = __ldg(&g_Ppre[(size_t)p * 32 + lane]);

    // point coords (scaled)
    float qxu = __ldg(&pv[p * 3 + 0]);
    float qyu = __ldg(&pv[p * 3 + 1]);
    float qzu = __ldg(&pv[p * 3 + 2]);
    float qx = __fmul_rn(qxu, 24.0f);
    float qy = __fmul_rn(qyu, 24.0f);
    float qz = __fmul_rn(qzu, 24.0f);
    float qq = __fadd_rn(__fadd_rn(__fmul_rn(qx, qx), __fmul_rn(qy, qy)), __fmul_rn(qz, qz));

    // ---- Phase A: set-only top-16 of 64 via 32-bit bitonic ----
    int ix0 = min(max((int)floorf((qxu + 1.0f) * 23.5f) - 1, 0), RES - 4);
    int iy0 = min(max((int)floorf((qyu + 1.0f) * 23.5f) - 1, 0), RES - 4);
    int iz0 = min(max((int)floorf((qzu + 1.0f) * 23.5f) - 1, 0), RES - 4);

    float dA = cand_dist(lane,      ix0, iy0, iz0, lins, qx, qy, qz, qq);
    float dB = cand_dist(lane + 32, ix0, iy0, iz0, lins, qx, qy, qz, qq);
    unsigned int k0 = (fmap(dA) & 0xFFFFFFC0u) | (unsigned int)lane;
    unsigned int k1 = (fmap(dB) & 0xFFFFFFC0u) | (unsigned int)(lane + 32);

    #pragma unroll
    for (int ks = 2; ks <= 32; ks <<= 1) {
        bool up = ((lane & ks) == 0);
        #pragma unroll
        for (int j = ks >> 1; j > 0; j >>= 1) {
            k0 = ce32(k0, j, up, lane);
            k1 = ce32(k1, j, up, lane);
        }
    }
    unsigned int k1r = __shfl_sync(0xffffffffu, k1, 31 - lane);
    unsigned int mn = min(k0, k1r);
    unsigned int mnp = __shfl_xor_sync(0xffffffffu, mn, 16);
    unsigned int low = min(mn, mnp);       // lanes 0-15: the top-16 set

    // ---- stash gm per slot ----
    const int gbase = ix0 * (RES * RES) + iy0 * RES + iz0;
    if (lane < KNN) {
        int t = (int)(low & 63u);
        int a = t >> 4, b = (t >> 2) & 3, c = t & 3;
        gms[w][lane] = gbase + a * (RES * RES) + b * RES + c;
    }
    __syncwarp();

    // ---- Phase B1: h1 = gelu(Ppre' + Gpre'), tf32, swizzled STS ----
    const u64* Gpreu = reinterpret_cast<const u64*>(g_Gpre);
    const uint32_t h1base = s2u(&h1s[w][0]);
    #pragma unroll 4
    for (int k = 0; k < KNN; ++k) {
        int gm = gms[w][k];
        u64 gp = __ldg(&Gpreu[(size_t)gm * 32 + lane]);
        u64 h = gelu2(add2(pre2, gp));
        float h0, h1f; unpack2(h, h0, h1f);
        uint32_t r0 = tf32r(h0), r1 = tf32r(h1f);
        uint32_t word = (uint32_t)(k * 64) + (((uint32_t)(2 * lane)) ^ (uint32_t)((4 * k) & 31));
        asm volatile("st.shared.v2.b32 [%0], {%1,%2};"
                     :: "r"(h1base + word * 4u), "r"(r0), "r"(r1));
    }
    __syncwarp();

    // ---- Phase B2: D(16x32) = h1(16x64) @ W2(64x32), bias-initialized ----
    float d0[4], d1[4], d2[4], d3[4];
    #pragma unroll
    for (int nt = 0; nt < 4; ++nt) {
        float bA = b2s[8 * nt + 2 * t4];
        float bB = b2s[8 * nt + 2 * t4 + 1];
        d0[nt] = bA; d1[nt] = bB; d2[nt] = bA; d3[nt] = bB;
    }
    {
        const uint32_t* h1u = &h1s[w][0];
        const ulonglong2* frs2 = reinterpret_cast<const ulonglong2*>(frs);
        const int xr = 4 * g4;
        #pragma unroll 2
        for (int s = 0; s < 8; ++s) {
            int c0 = 8 * s + t4;
            uint32_t a0 = h1u[g4 * 64 + (c0 ^ xr)];
            uint32_t a1 = h1u[(g4 + 8) * 64 + (c0 ^ xr)];
            uint32_t a2 = h1u[g4 * 64 + ((c0 + 4) ^ xr)];
            uint32_t a3 = h1u[(g4 + 8) * 64 + ((c0 + 4) ^ xr)];
            ulonglong2 q0 = frs2[(s * 32 + lane) * 2 + 0];
            ulonglong2 q1 = frs2[(s * 32 + lane) * 2 + 1];
            uint32_t b0, b1v;
            asm("mov.b64 {%0,%1}, %2;" : "=r"(b0), "=r"(b1v) : "l"(q0.x));
            mma_tf32(d0[0], d1[0], d2[0], d3[0], a0, a1, a2, a3, b0, b1v);
            asm("mov.b64 {%0,%1}, %2;" : "=r"(b0), "=r"(b1v) : "l"(q0.y));
            mma_tf32(d0[1], d1[1], d2[1], d3[1], a0, a1, a2, a3, b0, b1v);
            asm("mov.b64 {%0,%1}, %2;" : "=r"(b0), "=r"(b1v) : "l"(q1.x));
            mma_tf32(d0[2], d1[2], d2[2], d3[2], a0, a1, a2, a3, b0, b1v);
            asm("mov.b64 {%0,%1}, %2;" : "=r"(b0), "=r"(b1v) : "l"(q1.y));
            mma_tf32(d0[3], d1[3], d2[3], d3[3], a0, a1, a2, a3, b0, b1v);
        }
    }

    // ---- epilogue: gelu, mean over 16 edges ----
    const u64 HK2 = pack2(0.0625f, 0.0625f);
    #pragma unroll
    for (int nt = 0; nt < 4; ++nt) {
        u64 v = add2(gelu2(pack2(d0[nt], d1[nt])), gelu2(pack2(d2[nt], d3[nt])));
        v = add2(v, __shfl_xor_sync(0xffffffffu, v, 4));
        v = add2(v, __shfl_xor_sync(0xffffffffu, v, 8));
        v = add2(v, __shfl_xor_sync(0xffffffffu, v, 16));
        if (lane < 4) aggs[w][nt * 4 + lane] = mul2(v, HK2);
    }
    __syncwarp();

    // ---- out transform (packed) ----
    {
        const u64* ag = aggs[w];
        u64 acc2 = pack2(0.0f, 0.0f);
        #pragma unroll
        for (int i2 = 0; i2 < 16; ++i2)
            acc2 = fma2(ag[i2], __ldg(&g_W3p[i2 * 32 + lane]), acc2);
        float a0, a1; unpack2(acc2, a0, a1);
        float acc = __fadd_rn(__fadd_rn(a0, a1), b3s[lane]);
        out[(size_t)p * 32 + lane] = gelu_fast(acc);
    }
}

// ---------------------------------------------------------------------------
// launch
// ---------------------------------------------------------------------------
extern "C" void kernel_launch(void* const* d_in, const int* in_sizes, int n_in,
                              void* d_out, int out_size) {
    const float* gv = (const float*)d_in[0];
    const float* gf = (const float*)d_in[1];
    const float* pv = (const float*)d_in[2];
    const float* pf = (const float*)d_in[3];
    const float* W1 = (const float*)d_in[4];
    const float* b1 = (const float*)d_in[5];
    const float* W2 = (const float*)d_in[6];
    const float* b2 = (const float*)d_in[7];
    const float* W3 = (const float*)d_in[8];
    const float* b3 = (const float*)d_in[9];
    float* out = (float*)d_out;

    pre_kernel<<<GPRE_BLKS + PPRE_BLKS, 256>>>(gf, pf, gv, pv, W1, b1, W2, W3);
    fused_kernel<<<NPTS / 8, 256>>>(gv, pv, b2, b3, out);
}

// round 17
// speedup vs baseline: 1.1216x; 1.1216x over previous
#include <cuda_runtime.h>
#include <math.h>
#include <stdint.h>

// ---------------------------------------------------------------------------
// GridFeatureToPointGraphConv — R17: fused identical to R15/R16 (best, ~149us);
// pre_kernel amortized: 256 rows/block (4x fewer blocks, wcol preamble
// amortized over 32 passes). Numerics identical to R15.
// ---------------------------------------------------------------------------

#define RES 48
#define NGRID (RES*RES*RES)      // 110592
#define NPTS 65536
#define KNN 16
#define GPRE_BLKS (NGRID / 256)  // 432
#define PPRE_BLKS (NPTS / 256)   // 256

typedef unsigned long long u64;

__device__ float g_Gpre[NGRID * 64];    // 28.3 MB (L2-resident)
__device__ u64   g_Ppre[NPTS * 32];     // 16 MB
__device__ uint2 g_W2frag[8 * 32 * 4];  // per-lane tf32 B fragments [s][lane][nt]
__device__ u64   g_W3p[16 * 32];        // {W3[2i][o], W3[2i+1][o]}

// ---- f32x2 helpers -------------------------------------------------------
__device__ __forceinline__ u64 pack2(float lo, float hi) {
    u64 r; asm("mov.b64 %0, {%1,%2};" : "=l"(r) : "f"(lo), "f"(hi)); return r;
}
__device__ __forceinline__ void unpack2(u64 v, float& lo, float& hi) {
    asm("mov.b64 {%0,%1}, %2;" : "=f"(lo), "=f"(hi) : "l"(v));
}
__device__ __forceinline__ u64 fma2(u64 a, u64 b, u64 c) {
    u64 d; asm("fma.rn.f32x2 %0, %1, %2, %3;" : "=l"(d) : "l"(a), "l"(b), "l"(c)); return d;
}
__device__ __forceinline__ u64 mul2(u64 a, u64 b) {
    u64 d; asm("mul.rn.f32x2 %0, %1, %2;" : "=l"(d) : "l"(a), "l"(b)); return d;
}
__device__ __forceinline__ u64 add2(u64 a, u64 b) {
    u64 d; asm("add.rn.f32x2 %0, %1, %2;" : "=l"(d) : "l"(a), "l"(b)); return d;
}
__device__ __forceinline__ float ex2f(float x) {
    float r; asm("ex2.approx.f32 %0, %1;" : "=f"(r) : "f"(x)); return r;
}
__device__ __forceinline__ float rcpf(float x) {
    float r; asm("rcp.approx.f32 %0, %1;" : "=f"(r) : "f"(x)); return r;
}
__device__ __forceinline__ uint32_t s2u(const void* p) {
    return (uint32_t)__cvta_generic_to_shared(p);
}
__device__ __forceinline__ uint32_t tf32r(float x) {
    uint32_t r; asm("cvt.rna.tf32.f32 %0, %1;" : "=r"(r) : "f"(x)); return r;
}

// gelu_tanh(x) == x / (1 + e^{-p}), p = 1.5957691216x + 0.07135481681x^3
__device__ __forceinline__ float gelu_fast(float x) {
    float u = x * x;
    float w = __fmaf_rn(0.07135481681f, u, 1.5957691216f);
    float p = x * w;
    float e = __expf(-p);
    return __fdividef(x, 1.0f + e);
}
// paired gelu with -log2e folded into the polynomial
__device__ __forceinline__ u64 gelu2(u64 x) {
    const u64 C0 = pack2(-0.10295047642f, -0.10295047642f);
    const u64 C1 = pack2(-2.30258509299f, -2.30258509299f);
    const u64 ONE2 = pack2(1.0f, 1.0f);
    u64 u = mul2(x, x);
    u64 w = fma2(u, C0, C1);
    u64 m = mul2(x, w);
    float m0, m1; unpack2(m, m0, m1);
    u64 e = pack2(ex2f(m0), ex2f(m1));
    u64 den = add2(ONE2, e);
    float d0, d1; unpack2(den, d0, d1);
    u64 r = pack2(rcpf(d0), rcpf(d1));
    return mul2(x, r);
}

// tf32 mma m16n8k8
__device__ __forceinline__ void mma_tf32(float& d0, float& d1, float& d2, float& d3,
                                         uint32_t a0, uint32_t a1, uint32_t a2, uint32_t a3,
                                         uint32_t b0, uint32_t b1) {
    asm volatile(
        "mma.sync.aligned.m16n8k8.row.col.f32.tf32.tf32.f32 "
        "{%0,%1,%2,%3}, {%4,%5,%6,%7}, {%8,%9}, {%0,%1,%2,%3};"
        : "+f"(d0), "+f"(d1), "+f"(d2), "+f"(d3)
        : "r"(a0), "r"(a1), "r"(a2), "r"(a3), "r"(b0), "r"(b1));
}

// ---------------------------------------------------------------------------
// Kernel 1: merged pre-processing, 256 rows/block, rel-fold.
// ---------------------------------------------------------------------------
__global__ __launch_bounds__(256) void pre_kernel(const float* __restrict__ gf,
                                                  const float* __restrict__ pf,
                                                  const float* __restrict__ gv,
                                                  const float* __restrict__ pv,
                                                  const float* __restrict__ W1,
                                                  const float* __restrict__ b1,
                                                  const float* __restrict__ W2,
                                                  const float* __restrict__ W3) {
    __shared__ float linsS[RES];
    const int tid = threadIdx.x;
    const int bid = blockIdx.x;
    const int v = tid >> 5;
    const int o = tid & 31;

    if (tid < RES) linsS[tid] = __fmul_rn(__ldg(&gv[3 * tid + 2]), 24.0f);

    if (bid == 0) {
        for (int j = tid; j < 8 * 32 * 4; j += 256) {
            int s = j >> 7, ln = (j >> 2) & 31, nt = j & 3;
            int t = ln & 3, g = ln >> 2;
            uint2 vv;
            vv.x = tf32r(W2[(8 * s + t) * 32 + 8 * nt + g]);
            vv.y = tf32r(W2[(8 * s + t + 4) * 32 + 8 * nt + g]);
            g_W2frag[j] = vv;
        }
        for (int j = tid; j < 16 * 32; j += 256) {
            int i = j >> 5, oo = j & 31;
            g_W3p[j] = pack2(W3[(2 * i) * 32 + oo], W3[(2 * i + 1) * 32 + oo]);
        }
    }

    // rel-row pairs for this lane's channel pair
    const u64 wrx = pack2(W1[64 * 64 + 2 * o], W1[64 * 64 + 2 * o + 1]);
    const u64 wry = pack2(W1[65 * 64 + 2 * o], W1[65 * 64 + 2 * o + 1]);
    const u64 wrz = pack2(W1[66 * 64 + 2 * o], W1[66 * 64 + 2 * o + 1]);

    __syncthreads();

    if (bid < GPRE_BLKS) {
        u64 wcol[32];
        #pragma unroll
        for (int c = 0; c < 32; ++c)
            wcol[c] = __ldg(reinterpret_cast<const u64*>(W1 + c * 64 + 2 * o));
        const int base = bid * 256;
        u64* Gpreu = reinterpret_cast<u64*>(g_Gpre);
        #pragma unroll 4
        for (int pass = 0; pass < 32; ++pass) {
            const int g = base + pass * 8 + v;
            const float4* grow = reinterpret_cast<const float4*>(gf + (size_t)g * 32);
            u64 acc = pack2(0.0f, 0.0f);
            #pragma unroll
            for (int c4 = 0; c4 < 8; ++c4) {
                float4 f = __ldg(&grow[c4]);
                acc = fma2(pack2(f.x, f.x), wcol[4 * c4 + 0], acc);
                acc = fma2(pack2(f.y, f.y), wcol[4 * c4 + 1], acc);
                acc = fma2(pack2(f.z, f.z), wcol[4 * c4 + 2], acc);
                acc = fma2(pack2(f.w, f.w), wcol[4 * c4 + 3], acc);
            }
            int ixg = g / (RES * RES);
            int rem = g - ixg * (RES * RES);
            int iyg = rem / RES;
            int izg = rem - iyg * RES;
            float lx = linsS[ixg];
            float ly = linsS[iyg];
            float lz = linsS[izg];
            acc = fma2(pack2(lx, lx), wrx, acc);
            acc = fma2(pack2(ly, ly), wry, acc);
            acc = fma2(pack2(lz, lz), wrz, acc);
            Gpreu[(size_t)g * 32 + o] = acc;
        }
    } else {
        u64 wcol[32];
        #pragma unroll
        for (int c = 0; c < 32; ++c)
            wcol[c] = __ldg(reinterpret_cast<const u64*>(W1 + (32 + c) * 64 + 2 * o));
        const u64 b1v = __ldg(reinterpret_cast<const u64*>(b1 + 2 * o));
        const int base = (bid - GPRE_BLKS) * 256;
        #pragma unroll 4
        for (int pass = 0; pass < 32; ++pass) {
            const int p = base + pass * 8 + v;
            const float4* prow = reinterpret_cast<const float4*>(pf + (size_t)p * 32);
            u64 acc = b1v;
            #pragma unroll
            for (int c4 = 0; c4 < 8; ++c4) {
                float4 f = __ldg(&prow[c4]);
                acc = fma2(pack2(f.x, f.x), wcol[4 * c4 + 0], acc);
                acc = fma2(pack2(f.y, f.y), wcol[4 * c4 + 1], acc);
                acc = fma2(pack2(f.z, f.z), wcol[4 * c4 + 2], acc);
                acc = fma2(pack2(f.w, f.w), wcol[4 * c4 + 3], acc);
            }
            float nqx = __fmul_rn(__ldg(&pv[3 * p + 0]), -24.0f);
            float nqy = __fmul_rn(__ldg(&pv[3 * p + 1]), -24.0f);
            float nqz = __fmul_rn(__ldg(&pv[3 * p + 2]), -24.0f);
            acc = fma2(pack2(nqx, nqx), wrx, acc);
            acc = fma2(pack2(nqy, nqy), wry, acc);
            acc = fma2(pack2(nqz, nqz), wrz, acc);
            g_Ppre[(size_t)p * 32 + o] = acc;
        }
    }
}

// ---------------------------------------------------------------------------
// Selection helpers — 32-bit keys, set-only top-16 (R14)
// ---------------------------------------------------------------------------
__device__ __forceinline__ float cand_dist(int t, int ix0, int iy0, int iz0,
                                           const float* __restrict__ lins,
                                           float qx, float qy, float qz, float qq) {
    int a = t >> 4, b = (t >> 2) & 3, c = t & 3;
    float px = lins[ix0 + a], py = lins[iy0 + b], pz = lins[iz0 + c];
    float pp = __fadd_rn(__fadd_rn(__fmul_rn(px, px), __fmul_rn(py, py)), __fmul_rn(pz, pz));
    float dot = __fmaf_rn(qz, pz, __fmaf_rn(qy, py, __fmul_rn(qx, px)));
    return __fadd_rn(__fsub_rn(qq, __fadd_rn(dot, dot)), pp);
}
__device__ __forceinline__ unsigned int fmap(float d) {
    unsigned int b = __float_as_uint(d);
    return (b & 0x80000000u) ? ~b : (b | 0x80000000u);
}
__device__ __forceinline__ unsigned int ce32(unsigned int k, int j, bool up, int lane) {
    unsigned int pk = __shfl_xor_sync(0xffffffffu, k, j);
    unsigned int mn = min(k, pk);
    unsigned int mx = max(k, pk);
    bool lower = ((lane & j) == 0);
    return (lower == up) ? mn : mx;
}

// ---------------------------------------------------------------------------
// Kernel 2: fused. One warp per point; layer-2 via mma.sync tf32. (R15)
// ---------------------------------------------------------------------------
__global__ __launch_bounds__(256, 4) void fused_kernel(
    const float* __restrict__ gv,
    const float* __restrict__ pv,
    const float* __restrict__ b2,
    const float* __restrict__ b3,
    float* __restrict__ out)
{
    __shared__ float lins[RES];
    __shared__ float b2s[32];
    __shared__ float b3s[32];
    __shared__ __align__(16) uint2 frs[8 * 32 * 4];       // W2 fragments (8 KB)
    __shared__ __align__(16) uint32_t h1s[8][16 * 64];    // tf32 h1, XOR-swizzled
    __shared__ __align__(16) u64 aggs[8][16];
    __shared__ int gms[8][16];

    int tid = threadIdx.x;
    for (int j = tid; j < 8 * 32 * 4; j += 256) frs[j] = __ldg(&g_W2frag[j]);
    if (tid >= 128 && tid < 160) b2s[tid - 128] = b2[tid - 128];
    if (tid >= 160 && tid < 192) b3s[tid - 160] = b3[tid - 160];
    if (tid >= 192 && tid < 192 + RES)
        lins[tid - 192] = __fmul_rn(gv[3 * (tid - 192) + 2], 24.0f);
    __syncthreads();

    const int w = tid >> 5;
    const int lane = tid & 31;
    const int p = blockIdx.x * 8 + w;
    const int t4 = lane & 3;
    const int g4 = lane >> 2;

    // per-point layer-1 partial (precomputed, rel q-part folded in)
    u64 pre2 = __ldg(&g_Ppre[(size_t)p * 32 + lane]);

    // point coords (scaled)
    float qxu = __ldg(&pv[p * 3 + 0]);
    float qyu = __ldg(&pv[p * 3 + 1]);
    float qzu = __ldg(&pv[p * 3 + 2]);
    float qx = __fmul_rn(qxu, 24.0f);
    float qy = __fmul_rn(qyu, 24.0f);
    float qz = __fmul_rn(qzu, 24.0f);
    float qq = __fadd_rn(__fadd_rn(__fmul_rn(qx, qx), __fmul_rn(qy, qy)), __fmul_rn(qz, qz));

    // ---- Phase A: set-only top-16 of 64 via 32-bit bitonic ----
    int ix0 = min(max((int)floorf((qxu + 1.0f) * 23.5f) - 1, 0), RES - 4);
    int iy0 = min(max((int)floorf((qyu + 1.0f) * 23.5f) - 1, 0), RES - 4);
    int iz0 = min(max((int)floorf((qzu + 1.0f) * 23.5f) - 1, 0), RES - 4);

    float dA = cand_dist(lane,      ix0, iy0, iz0, lins, qx, qy, qz, qq);
    float dB = cand_dist(lane + 32, ix0, iy0, iz0, lins, qx, qy, qz, qq);
    unsigned int k0 = (fmap(dA) & 0xFFFFFFC0u) | (unsigned int)lane;
    unsigned int k1 = (fmap(dB) & 0xFFFFFFC0u) | (unsigned int)(lane + 32);

    #pragma unroll
    for (int ks = 2; ks <= 32; ks <<= 1) {
        bool up = ((lane & ks) == 0);
        #pragma unroll
        for (int j = ks >> 1; j > 0; j >>= 1) {
            k0 = ce32(k0, j, up, lane);
            k1 = ce32(k1, j, up, lane);
        }
    }
    unsigned int k1r = __shfl_sync(0xffffffffu, k1, 31 - lane);
    unsigned int mn = min(k0, k1r);
    unsigned int mnp = __shfl_xor_sync(0xffffffffu, mn, 16);
    unsigned int low = min(mn, mnp);       // lanes 0-15: the top-16 set

    // ---- stash gm per slot ----
    const int gbase = ix0 * (RES * RES) + iy0 * RES + iz0;
    if (lane < KNN) {
        int t = (int)(low & 63u);
        int a = t >> 4, b = (t >> 2) & 3, c = t & 3;
        gms[w][lane] = gbase + a * (RES * RES) + b * RES + c;
    }
    __syncwarp();

    // ---- Phase B1: h1 = gelu(Ppre' + Gpre'), tf32, swizzled STS ----
    const u64* Gpreu = reinterpret_cast<const u64*>(g_Gpre);
    const uint32_t h1base = s2u(&h1s[w][0]);
    #pragma unroll 4
    for (int k = 0; k < KNN; ++k) {
        int gm = gms[w][k];
        u64 gp = __ldg(&Gpreu[(size_t)gm * 32 + lane]);
        u64 h = gelu2(add2(pre2, gp));
        float h0, h1f; unpack2(h, h0, h1f);
        uint32_t r0 = tf32r(h0), r1 = tf32r(h1f);
        uint32_t word = (uint32_t)(k * 64) + (((uint32_t)(2 * lane)) ^ (uint32_t)((4 * k) & 31));
        asm volatile("st.shared.v2.b32 [%0], {%1,%2};"
                     :: "r"(h1base + word * 4u), "r"(r0), "r"(r1));
    }
    __syncwarp();

    // ---- Phase B2: D(16x32) = h1(16x64) @ W2(64x32), bias-initialized ----
    float d0[4], d1[4], d2[4], d3[4];
    #pragma unroll
    for (int nt = 0; nt < 4; ++nt) {
        float bA = b2s[8 * nt + 2 * t4];
        float bB = b2s[8 * nt + 2 * t4 + 1];
        d0[nt] = bA; d1[nt] = bB; d2[nt] = bA; d3[nt] = bB;
    }
    {
        const uint32_t* h1u = &h1s[w][0];
        const ulonglong2* frs2 = reinterpret_cast<const ulonglong2*>(frs);
        const int xr = 4 * g4;
        #pragma unroll 2
        for (int s = 0; s < 8; ++s) {
            int c0 = 8 * s + t4;
            uint32_t a0 = h1u[g4 * 64 + (c0 ^ xr)];
            uint32_t a1 = h1u[(g4 + 8) * 64 + (c0 ^ xr)];
            uint32_t a2 = h1u[g4 * 64 + ((c0 + 4) ^ xr)];
            uint32_t a3 = h1u[(g4 + 8) * 64 + ((c0 + 4) ^ xr)];
            ulonglong2 q0 = frs2[(s * 32 + lane) * 2 + 0];
            ulonglong2 q1 = frs2[(s * 32 + lane) * 2 + 1];
            uint32_t b0, b1v;
            asm("mov.b64 {%0,%1}, %2;" : "=r"(b0), "=r"(b1v) : "l"(q0.x));
            mma_tf32(d0[0], d1[0], d2[0], d3[0], a0, a1, a2, a3, b0, b1v);
            asm("mov.b64 {%0,%1}, %2;" : "=r"(b0), "=r"(b1v) : "l"(q0.y));
            mma_tf32(d0[1], d1[1], d2[1], d3[1], a0, a1, a2, a3, b0, b1v);
            asm("mov.b64 {%0,%1}, %2;" : "=r"(b0), "=r"(b1v) : "l"(q1.x));
            mma_tf32(d0[2], d1[2], d2[2], d3[2], a0, a1, a2, a3, b0, b1v);
            asm("mov.b64 {%0,%1}, %2;" : "=r"(b0), "=r"(b1v) : "l"(q1.y));
            mma_tf32(d0[3], d1[3], d2[3], d3[3], a0, a1, a2, a3, b0, b1v);
        }
    }

    // ---- epilogue: gelu, mean over 16 edges ----
    const u64 HK2 = pack2(0.0625f, 0.0625f);
    #pragma unroll
    for (int nt = 0; nt < 4; ++nt) {
        u64 v = add2(gelu2(pack2(d0[nt], d1[nt])), gelu2(pack2(d2[nt], d3[nt])));
        v = add2(v, __shfl_xor_sync(0xffffffffu, v, 4));
        v = add2(v, __shfl_xor_sync(0xffffffffu, v, 8));
        v = add2(v, __shfl_xor_sync(0xffffffffu, v, 16));
        if (lane < 4) aggs[w][nt * 4 + lane] = mul2(v, HK2);
    }
    __syncwarp();

    // ---- out transform (packed) ----
    {
        const u64* ag = aggs[w];
        u64 acc2 = pack2(0.0f, 0.0f);
        #pragma unroll
        for (int i2 = 0; i2 < 16; ++i2)
            acc2 = fma2(ag[i2], __ldg(&g_W3p[i2 * 32 + lane]), acc2);
        float a0, a1; unpack2(acc2, a0, a1);
        float acc = __fadd_rn(__fadd_rn(a0, a1), b3s[lane]);
        out[(size_t)p * 32 + lane] = gelu_fast(acc);
    }
}

// ---------------------------------------------------------------------------
// launch
// ---------------------------------------------------------------------------
extern "C" void kernel_launch(void* const* d_in, const int* in_sizes, int n_in,
                              void* d_out, int out_size) {
    const float* gv = (const float*)d_in[0];
    const float* gf = (const float*)d_in[1];
    const float* pv = (const float*)d_in[2];
    const float* pf = (const float*)d_in[3];
    const float* W1 = (const float*)d_in[4];
    const float* b1 = (const float*)d_in[5];
    const float* W2 = (const float*)d_in[6];
    const float* b2 = (const float*)d_in[7];
    const float* W3 = (const float*)d_in[8];
    const float* b3 = (const float*)d_in[9];
    float* out = (float*)d_out;

    pre_kernel<<<GPRE_BLKS + PPRE_BLKS, 256>>>(gf, pf, gv, pv, W1, b1, W2, W3);
    fused_kernel<<<NPTS / 8, 256>>>(gv, pv, b2, b3, out);
}